// round 2
// baseline (speedup 1.0000x reference)
#include <cuda_runtime.h>
#include <cstdint>

// ============================================================================
// y[m,o] = fq_tok(x)[m,:] . fq_ch(w)[o,:] + b[o]
//   fq value = q * s, q integer in [-128,127]:
//   y[m,o] = sx[m]*sw[o]*(sum_k qx[m,k]*qw[o,k]) + b[o]
// Exact int8 GEMM via legacy mma.sync (family-portable PTX; tcgen05 is
// unavailable because the harness emits compute_103 family PTX).
// M = 8192 (derived), N = 4096, K = 4096.
// ============================================================================

#define MAX_M 8192
#define NN 4096
#define KK 4096

__device__ int8_t g_qx[(size_t)MAX_M * KK];   // 32 MB
__device__ int8_t g_qw[(size_t)NN * KK];      // 16 MB
__device__ float g_sx[MAX_M];
__device__ float g_sw[NN];

// ---------------------------------------------------------------------------
// PTX helpers (all family-portable: sm_80+ baseline ISA)
// ---------------------------------------------------------------------------
__device__ __forceinline__ uint32_t smem_u32(const void* p) {
    uint32_t a;
    asm("{ .reg .u64 t; cvta.to.shared.u64 t, %1; cvt.u32.u64 %0, t; }" : "=r"(a) : "l"(p));
    return a;
}

#define CP_ASYNC16(smem, gptr) \
    asm volatile("cp.async.cg.shared.global [%0], [%1], 16;" \
        :: "r"((uint32_t)(smem)), "l"(gptr) : "memory")
#define CP_COMMIT() asm volatile("cp.async.commit_group;" ::: "memory")
#define CP_WAIT(n)  asm volatile("cp.async.wait_group %0;" :: "n"(n) : "memory")

#define LDSM_X4(r0, r1, r2, r3, addr) \
    asm volatile("ldmatrix.sync.aligned.m8n8.x4.shared.b16 {%0,%1,%2,%3}, [%4];" \
        : "=r"(r0), "=r"(r1), "=r"(r2), "=r"(r3) : "r"((uint32_t)(addr)))
#define LDSM_X2(r0, r1, addr) \
    asm volatile("ldmatrix.sync.aligned.m8n8.x2.shared.b16 {%0,%1}, [%2];" \
        : "=r"(r0), "=r"(r1) : "r"((uint32_t)(addr)))

#define MMA_S8(d, a, b) \
    asm volatile("mma.sync.aligned.m16n8k32.row.col.s32.s8.s8.s32 " \
        "{%0,%1,%2,%3},{%4,%5,%6,%7},{%8,%9},{%0,%1,%2,%3};" \
        : "+r"((d)[0]), "+r"((d)[1]), "+r"((d)[2]), "+r"((d)[3]) \
        : "r"((a)[0]), "r"((a)[1]), "r"((a)[2]), "r"((a)[3]), "r"((b)[0]), "r"((b)[1]))

// ---------------------------------------------------------------------------
// Kernel 1: per-row symmetric fake-quant -> int8 + fp32 scale.
// One 256-thread block per row (K = 4096 = 256 threads * 16 elems).
// ---------------------------------------------------------------------------
__global__ __launch_bounds__(256) void quant_rows(const float* __restrict__ in, int to_x) {
    int8_t* qout = to_x ? g_qx : g_qw;
    float* sout = to_x ? g_sx : g_sw;

    const int row = blockIdx.x;
    const int t = threadIdx.x;
    const float4* src = reinterpret_cast<const float4*>(in) + (size_t)row * (KK / 4);

    float4 v[4];
    float am = 0.f;
#pragma unroll
    for (int j = 0; j < 4; j++) {
        v[j] = src[t + j * 256];
        am = fmaxf(am, fmaxf(fmaxf(fabsf(v[j].x), fabsf(v[j].y)),
                             fmaxf(fabsf(v[j].z), fabsf(v[j].w))));
    }
#pragma unroll
    for (int o = 16; o; o >>= 1) am = fmaxf(am, __shfl_xor_sync(0xffffffffu, am, o));

    __shared__ float s_red[8];
    __shared__ float s_scale;
    if ((t & 31) == 0) s_red[t >> 5] = am;
    __syncthreads();
    if (t < 8) {
        float a = s_red[t];
#pragma unroll
        for (int o = 4; o; o >>= 1) a = fmaxf(a, __shfl_xor_sync(0xffu, a, o));
        if (t == 0) {
            float sc = fmaxf(a / 127.0f, 1e-8f);
            s_scale = sc;
            sout[row] = sc;
        }
    }
    __syncthreads();
    const float inv = 1.0f / s_scale;

    uint32_t* qrow = reinterpret_cast<uint32_t*>(qout + (size_t)row * KK);
#pragma unroll
    for (int j = 0; j < 4; j++) {
        int q0 = min(max(__float2int_rn(v[j].x * inv), -128), 127);
        int q1 = min(max(__float2int_rn(v[j].y * inv), -128), 127);
        int q2 = min(max(__float2int_rn(v[j].z * inv), -128), 127);
        int q3 = min(max(__float2int_rn(v[j].w * inv), -128), 127);
        qrow[t + j * 256] = (uint32_t)(q0 & 0xff) | ((uint32_t)(q1 & 0xff) << 8) |
                            ((uint32_t)(q2 & 0xff) << 16) | ((uint32_t)q3 << 24);
    }
}

// ---------------------------------------------------------------------------
// Kernel 2: int8 GEMM, C[m,o] = sum_k qx[m,k]*qw[o,k]; epilogue applies scales.
// BM=BN=128, BK=64 int8. 256 threads = 8 warps in a 4(M) x 2(N) grid,
// warp tile 32x64. 4-stage cp.async pipeline. SMEM row stride 80B (pad) =>
// conflict-free ldmatrix.
// ---------------------------------------------------------------------------
#define STAGES 4
#define STAGE_BYTES (2 * 128 * 80)   // A tile + B tile, 80B padded rows

__global__ __launch_bounds__(256, 2) void gemm_kernel(const float* __restrict__ bias,
                                                      float* __restrict__ out) {
    constexpr int KT = KK / 64;   // 64 main-loop iterations

    extern __shared__ char sm[];
    __shared__ float s_sw[128];
    __shared__ float s_bias[128];

    const int t = threadIdx.x;
    const int lane = t & 31;
    const int wid = t >> 5;
    const int warpM = wid & 3;    // 0..3
    const int warpN = wid >> 2;   // 0..1
    const int m0 = blockIdx.y * 128;
    const int n0 = blockIdx.x * 128;

    if (t < 128) {
        s_sw[t] = g_sw[n0 + t];
        s_bias[t] = bias[n0 + t];
    }

    const int8_t* gA = g_qx + (size_t)m0 * KK;
    const int8_t* gB = g_qw + (size_t)n0 * KK;
    const uint32_t smbase = smem_u32(sm);

    // cp.async mapping: 512 16B chunks per tile, 2 per thread per tile.
    const int crow = t >> 2;      // 0..63 (chunk j adds 64)
    const int ccol = t & 3;       // 16B column within 64B of K

    auto issue = [&](int it) {
        const int s = it % STAGES;
        const uint32_t sa = smbase + s * STAGE_BYTES;
        const uint32_t sb = sa + 128 * 80;
        const int koff = it * 64 + ccol * 16;
#pragma unroll
        for (int j = 0; j < 2; j++) {
            const int r = crow + j * 64;
            const uint32_t so = (uint32_t)r * 80u + (uint32_t)ccol * 16u;
            CP_ASYNC16(sa + so, gA + (size_t)r * KK + koff);
            CP_ASYNC16(sb + so, gB + (size_t)r * KK + koff);
        }
    };

    // Prologue: STAGES-1 stages in flight
#pragma unroll
    for (int it = 0; it < STAGES - 1; ++it) {
        issue(it);
        CP_COMMIT();
    }

    int acc[2][8][4];
#pragma unroll
    for (int mt = 0; mt < 2; mt++)
#pragma unroll
        for (int nt = 0; nt < 8; nt++)
#pragma unroll
            for (int i = 0; i < 4; i++) acc[mt][nt][i] = 0;

    // Per-thread ldmatrix base offsets (within a stage)
    const uint32_t a_off =
        (uint32_t)(warpM * 32 + (lane & 7) + ((lane >> 3) & 1) * 8) * 80u +
        (uint32_t)(lane >> 4) * 16u;
    const uint32_t b_off =
        (uint32_t)(warpN * 64 + (lane & 7)) * 80u + (uint32_t)((lane >> 3) & 1) * 16u;

    for (int it = 0; it < KT; ++it) {
        CP_WAIT(STAGES - 2);
        __syncthreads();

        const int nit = it + STAGES - 1;
        if (nit < KT) issue(nit);
        CP_COMMIT();

        const uint32_t sa = smbase + (it % STAGES) * STAGE_BYTES;
        const uint32_t sb = sa + 128 * 80;

#pragma unroll
        for (int s = 0; s < 2; ++s) {           // two k32 steps per BK=64
            uint32_t a[2][4], b[8][2];
#pragma unroll
            for (int mt = 0; mt < 2; mt++) {
                LDSM_X4(a[mt][0], a[mt][1], a[mt][2], a[mt][3],
                        sa + a_off + (uint32_t)mt * (16u * 80u) + (uint32_t)s * 32u);
            }
#pragma unroll
            for (int nt = 0; nt < 8; nt++) {
                LDSM_X2(b[nt][0], b[nt][1],
                        sb + b_off + (uint32_t)nt * (8u * 80u) + (uint32_t)s * 32u);
            }
#pragma unroll
            for (int mt = 0; mt < 2; mt++)
#pragma unroll
                for (int nt = 0; nt < 8; nt++) MMA_S8(acc[mt][nt], a[mt], b[nt]);
        }
    }

    // Epilogue: y = acc * sx[m] * sw[o] + b[o]
#pragma unroll
    for (int mt = 0; mt < 2; mt++) {
        const int r0 = warpM * 32 + mt * 16 + (lane >> 2);
        const float sx0 = g_sx[m0 + r0];
        const float sx1 = g_sx[m0 + r0 + 8];
        float* o0 = out + (size_t)(m0 + r0) * NN + n0;
        float* o1 = o0 + (size_t)8 * NN;
#pragma unroll
        for (int nt = 0; nt < 8; nt++) {
            const int lc = warpN * 64 + nt * 8 + (lane & 3) * 2;
            const float w0 = s_sw[lc], w1 = s_sw[lc + 1];
            const float bb0 = s_bias[lc], bb1 = s_bias[lc + 1];
            float2 v0, v1;
            v0.x = fmaf((float)acc[mt][nt][0] * sx0, w0, bb0);
            v0.y = fmaf((float)acc[mt][nt][1] * sx0, w1, bb1);
            v1.x = fmaf((float)acc[mt][nt][2] * sx1, w0, bb0);
            v1.y = fmaf((float)acc[mt][nt][3] * sx1, w1, bb1);
            *reinterpret_cast<float2*>(o0 + lc) = v0;
            *reinterpret_cast<float2*>(o1 + lc) = v1;
        }
    }
}

// ---------------------------------------------------------------------------
// Launch
// ---------------------------------------------------------------------------
extern "C" void kernel_launch(void* const* d_in, const int* in_sizes, int n_in,
                              void* d_out, int out_size) {
    const float* x = (const float*)d_in[0];   // [M, 4096]
    const float* w = (const float*)d_in[1];   // [4096, 4096]
    const float* b = (const float*)d_in[2];   // [4096]
    float* out = (float*)d_out;               // [M, 4096]

    const int M = in_sizes[0] / KK;           // 8192

    quant_rows<<<M, 256>>>(x, 1);
    quant_rows<<<NN, 256>>>(w, 0);

    static_assert(STAGES * STAGE_BYTES == 81920, "smem layout");
    cudaFuncSetAttribute(gemm_kernel, cudaFuncAttributeMaxDynamicSharedMemorySize,
                         STAGES * STAGE_BYTES);

    dim3 grid(NN / 128, M / 128);             // (32, 64)
    gemm_kernel<<<grid, 256, STAGES * STAGE_BYTES>>>(b, out);
}